// round 1
// baseline (speedup 1.0000x reference)
#include <cuda_runtime.h>

#define D_MODEL 512
#define NH 8
#define DH 64

// Scratch (allocation-free rule: __device__ globals). 4 x 8MB.
__device__ float g_q[4096 * 512];
__device__ float g_k[4096 * 512];
__device__ float g_v[4096 * 512];
__device__ float g_att[4096 * 512];

// ---------------------------------------------------------------------------
// C[M,512] = A[M,512] @ W[512,512]^T   (nn.Linear, bias=False)
// 64x64 block tile, 256 threads, 4x4 per thread, BK=16.
// ---------------------------------------------------------------------------
__global__ __launch_bounds__(256) void gemm_xwT(const float* __restrict__ A,
                                                const float* __restrict__ W,
                                                float* __restrict__ C) {
    __shared__ float Ash[64][17];
    __shared__ float Wsh[64][17];
    const int K = D_MODEL;
    const int tid = threadIdx.x;
    const int tx = tid & 15, ty = tid >> 4;
    const int row0 = blockIdx.x * 64, col0 = blockIdx.y * 64;
    const int lr = tid >> 2, lc = (tid & 3) * 4;

    float acc[4][4];
#pragma unroll
    for (int i = 0; i < 4; i++)
#pragma unroll
        for (int j = 0; j < 4; j++) acc[i][j] = 0.f;

    for (int k0 = 0; k0 < K; k0 += 16) {
        float4 av = *(const float4*)(A + (size_t)(row0 + lr) * K + k0 + lc);
        float4 wv = *(const float4*)(W + (size_t)(col0 + lr) * K + k0 + lc);
        __syncthreads();
        Ash[lr][lc + 0] = av.x; Ash[lr][lc + 1] = av.y;
        Ash[lr][lc + 2] = av.z; Ash[lr][lc + 3] = av.w;
        Wsh[lr][lc + 0] = wv.x; Wsh[lr][lc + 1] = wv.y;
        Wsh[lr][lc + 2] = wv.z; Wsh[lr][lc + 3] = wv.w;
        __syncthreads();
#pragma unroll
        for (int kk = 0; kk < 16; kk++) {
            float a[4], b[4];
#pragma unroll
            for (int i = 0; i < 4; i++) a[i] = Ash[ty * 4 + i][kk];
#pragma unroll
            for (int j = 0; j < 4; j++) b[j] = Wsh[tx * 4 + j][kk];
#pragma unroll
            for (int i = 0; i < 4; i++)
#pragma unroll
                for (int j = 0; j < 4; j++) acc[i][j] += a[i] * b[j];
        }
    }
#pragma unroll
    for (int i = 0; i < 4; i++) {
        float* crow = C + (size_t)(row0 + ty * 4 + i) * D_MODEL + col0 + tx * 4;
#pragma unroll
        for (int j = 0; j < 4; j++) crow[j] = acc[i][j];
    }
}

// ---------------------------------------------------------------------------
// Flash attention, fp32. One block = one (b,h, 64-row query tile).
// Br=Bc=64, 256 threads (16x16), 4x4 score fragment per thread.
// Causal: kb in [0, qb]. P tile reuses the K smem tile.
// Layouts are [B*S, D] rows with head columns h*64..h*64+63 (no transpose pass).
// ---------------------------------------------------------------------------
#define SMEM_ATTN ((64 * 65 * 2 + 64 * 64) * 4)

__global__ __launch_bounds__(256) void attn_kernel(const float* __restrict__ Qg,
                                                   const float* __restrict__ Kg,
                                                   const float* __restrict__ Vg,
                                                   float* __restrict__ Og,
                                                   int SEQ) {
    extern __shared__ float sm[];
    float* Qs = sm;                 // [64][65]
    float* Ks = sm + 64 * 65;       // [64][65], reused for P
    float* Vs = sm + 2 * 64 * 65;   // [64][64]

    const float inv_scale = 0.044194173824159216f;  // 1/sqrt(512)
    const int tid = threadIdx.x;
    const int tx = tid & 15, ty = tid >> 4;
    const int qb = gridDim.x - 1 - blockIdx.x;      // heavy (long) tiles first
    const int bh = blockIdx.y;
    const int b = bh / NH, h = bh % NH;
    const size_t rowbase = (size_t)b * SEQ;
    const int colh = h * DH;

    // Load Q tile [64 x 64] into padded smem
    {
        const int r = tid >> 2;
        const int cbase = (tid & 3) * 4;
#pragma unroll
        for (int rep = 0; rep < 4; rep++) {
            const int c = cbase + rep * 16;
            float4 v = *(const float4*)(Qg + (rowbase + qb * 64 + r) * D_MODEL + colh + c);
            Qs[r * 65 + c + 0] = v.x; Qs[r * 65 + c + 1] = v.y;
            Qs[r * 65 + c + 2] = v.z; Qs[r * 65 + c + 3] = v.w;
        }
    }

    float m[4], l[4], acc[4][4];
#pragma unroll
    for (int i = 0; i < 4; i++) {
        m[i] = -1e30f; l[i] = 0.f;
#pragma unroll
        for (int j = 0; j < 4; j++) acc[i][j] = 0.f;
    }

    for (int kb = 0; kb <= qb; kb++) {
        __syncthreads();  // prior tile fully consumed (Ks-as-P, Vs)
        {
            const int r = tid >> 2;
            const int cbase = (tid & 3) * 4;
#pragma unroll
            for (int rep = 0; rep < 4; rep++) {
                const int c = cbase + rep * 16;
                float4 kv = *(const float4*)(Kg + (rowbase + kb * 64 + r) * D_MODEL + colh + c);
                Ks[r * 65 + c + 0] = kv.x; Ks[r * 65 + c + 1] = kv.y;
                Ks[r * 65 + c + 2] = kv.z; Ks[r * 65 + c + 3] = kv.w;
                float4 vv = *(const float4*)(Vg + (rowbase + kb * 64 + r) * D_MODEL + colh + c);
                Vs[r * 64 + c + 0] = vv.x; Vs[r * 64 + c + 1] = vv.y;
                Vs[r * 64 + c + 2] = vv.z; Vs[r * 64 + c + 3] = vv.w;
            }
        }
        __syncthreads();

        // S = Q K^T  (64x64x64 fragment GEMM)
        float s[4][4];
#pragma unroll
        for (int i = 0; i < 4; i++)
#pragma unroll
            for (int j = 0; j < 4; j++) s[i][j] = 0.f;

#pragma unroll 4
        for (int d = 0; d < 64; d++) {
            float a[4], bv[4];
#pragma unroll
            for (int i = 0; i < 4; i++) a[i] = Qs[(ty * 4 + i) * 65 + d];
#pragma unroll
            for (int j = 0; j < 4; j++) bv[j] = Ks[(tx * 4 + j) * 65 + d];
#pragma unroll
            for (int i = 0; i < 4; i++)
#pragma unroll
                for (int j = 0; j < 4; j++) s[i][j] += a[i] * bv[j];
        }

        // scale + causal mask (diagonal tile only). Reference's (x-1e10)/scale
        // underflows expf to exactly 0, same as -1e30 here.
        const bool diag = (kb == qb);
#pragma unroll
        for (int i = 0; i < 4; i++)
#pragma unroll
            for (int j = 0; j < 4; j++) {
                float sv = s[i][j] * inv_scale;
                if (diag && (tx * 4 + j) > (ty * 4 + i)) sv = -1e30f;
                s[i][j] = sv;
            }

        // online softmax (row reductions across the 16 tx lanes)
#pragma unroll
        for (int i = 0; i < 4; i++) {
            float mloc = fmaxf(fmaxf(s[i][0], s[i][1]), fmaxf(s[i][2], s[i][3]));
#pragma unroll
            for (int o = 1; o < 16; o <<= 1)
                mloc = fmaxf(mloc, __shfl_xor_sync(0xffffffffu, mloc, o));
            const float mnew = fmaxf(m[i], mloc);
            const float sc = __expf(m[i] - mnew);
            float ls = 0.f;
#pragma unroll
            for (int j = 0; j < 4; j++) {
                s[i][j] = __expf(s[i][j] - mnew);
                ls += s[i][j];
            }
#pragma unroll
            for (int o = 1; o < 16; o <<= 1)
                ls += __shfl_xor_sync(0xffffffffu, ls, o);
            l[i] = l[i] * sc + ls;
            m[i] = mnew;
#pragma unroll
            for (int j = 0; j < 4; j++) acc[i][j] *= sc;
        }

        __syncthreads();  // everyone done reading Ks before P overwrite
#pragma unroll
        for (int i = 0; i < 4; i++)
#pragma unroll
            for (int j = 0; j < 4; j++)
                Ks[(ty * 4 + i) * 65 + tx * 4 + j] = s[i][j];
        __syncthreads();

        // O += P V   (64x64x64 fragment GEMM)
#pragma unroll 4
        for (int jj = 0; jj < 64; jj++) {
            float a[4];
#pragma unroll
            for (int i = 0; i < 4; i++) a[i] = Ks[(ty * 4 + i) * 65 + jj];
            float4 bv4 = *(const float4*)&Vs[jj * 64 + tx * 4];
            const float bv[4] = {bv4.x, bv4.y, bv4.z, bv4.w};
#pragma unroll
            for (int i = 0; i < 4; i++)
#pragma unroll
                for (int j = 0; j < 4; j++) acc[i][j] += a[i] * bv[j];
        }
    }

#pragma unroll
    for (int i = 0; i < 4; i++) {
        const float invl = 1.f / l[i];
        float* orow = Og + (rowbase + qb * 64 + ty * 4 + i) * D_MODEL + colh + tx * 4;
#pragma unroll
        for (int j = 0; j < 4; j++) orow[j] = acc[i][j] * invl;
    }
}

// ---------------------------------------------------------------------------
extern "C" void kernel_launch(void* const* d_in, const int* in_sizes, int n_in,
                              void* d_out, int out_size) {
    const float* q  = (const float*)d_in[0];
    const float* k  = (const float*)d_in[1];
    const float* v  = (const float*)d_in[2];
    const float* wq = (const float*)d_in[3];
    const float* wk = (const float*)d_in[4];
    const float* wv = (const float*)d_in[5];
    const float* wo = (const float*)d_in[6];
    float* out = (float*)d_out;

    const int M = in_sizes[0] / D_MODEL;  // B*S = 4096
    const int B = 2;
    const int SEQ = M / B;                // 2048

    float *gq, *gk, *gv, *ga;
    cudaGetSymbolAddress((void**)&gq, g_q);
    cudaGetSymbolAddress((void**)&gk, g_k);
    cudaGetSymbolAddress((void**)&gv, g_v);
    cudaGetSymbolAddress((void**)&ga, g_att);

    dim3 gg(M / 64, D_MODEL / 64);
    gemm_xwT<<<gg, 256>>>(q, wq, gq);
    gemm_xwT<<<gg, 256>>>(k, wk, gk);
    gemm_xwT<<<gg, 256>>>(v, wv, gv);

    static bool attr_set = false;
    if (!attr_set) {
        cudaFuncSetAttribute(attn_kernel,
                             cudaFuncAttributeMaxDynamicSharedMemorySize,
                             SMEM_ATTN);
        attr_set = true;
    }
    dim3 ag(SEQ / 64, B * NH);
    attn_kernel<<<ag, 256, SMEM_ATTN>>>(gq, gk, gv, ga, SEQ);

    gemm_xwT<<<gg, 256>>>(ga, wo, out);
}

// round 3
// speedup vs baseline: 3.1083x; 3.1083x over previous
#include <cuda_runtime.h>
#include <cstdint>

#define D_MODEL 512
#define NH 8
#define DH 64

// Scratch (allocation-free rule: __device__ globals). 4 x 8MB.
__device__ float g_q[4096 * 512];
__device__ float g_k[4096 * 512];
__device__ float g_v[4096 * 512];
__device__ float g_att[4096 * 512];

__device__ __forceinline__ float f2tf32(float x) {
    uint32_t y;
    asm("cvt.rna.tf32.f32 %0, %1;" : "=r"(y) : "f"(x));
    return __uint_as_float(y);
}

__device__ __forceinline__ void mma_tf32(float* c, uint32_t a0, uint32_t a1,
                                         uint32_t a2, uint32_t a3, uint32_t b0,
                                         uint32_t b1) {
    asm volatile(
        "mma.sync.aligned.m16n8k8.row.col.f32.tf32.tf32.f32 "
        "{%0,%1,%2,%3}, {%4,%5,%6,%7}, {%8,%9}, {%0,%1,%2,%3};"
        : "+f"(c[0]), "+f"(c[1]), "+f"(c[2]), "+f"(c[3])
        : "r"(a0), "r"(a1), "r"(a2), "r"(a3), "r"(b0), "r"(b1));
}

// ---------------------------------------------------------------------------
// C[M,512] = A[M,512] @ W[512,512]^T   via tf32 mma.
// BM=128, BN=64, BK=32. 256 threads = 8 warps (4 m x 2 n), warp tile 32x32.
// ---------------------------------------------------------------------------
#define GSTR 36
__global__ __launch_bounds__(256) void gemm_xwT(const float* __restrict__ A,
                                                const float* __restrict__ W,
                                                float* __restrict__ C) {
    __shared__ float As[128 * GSTR];
    __shared__ float Ws[64 * GSTR];
    const int tid = threadIdx.x;
    const int lane = tid & 31, wid = tid >> 5;
    const int g = lane >> 2, tg = lane & 3;
    const int warp_m = wid & 3, warp_n = wid >> 2;
    const int row0 = blockIdx.x * 128, col0 = blockIdx.y * 64;

    float acc[2][4][4];
#pragma unroll
    for (int mi = 0; mi < 2; mi++)
#pragma unroll
        for (int ni = 0; ni < 4; ni++)
#pragma unroll
            for (int c = 0; c < 4; c++) acc[mi][ni][c] = 0.f;

    for (int k0 = 0; k0 < D_MODEL; k0 += 32) {
        __syncthreads();
        // A tile: 128x32 (1024 float4), 4 per thread
#pragma unroll
        for (int i = 0; i < 4; i++) {
            const int f4 = tid + i * 256;
            const int r = f4 >> 3, c = (f4 & 7) * 4;
            float4 v = *(const float4*)(A + (size_t)(row0 + r) * D_MODEL + k0 + c);
            As[r * GSTR + c + 0] = f2tf32(v.x);
            As[r * GSTR + c + 1] = f2tf32(v.y);
            As[r * GSTR + c + 2] = f2tf32(v.z);
            As[r * GSTR + c + 3] = f2tf32(v.w);
        }
        // W tile: 64x32 (512 float4), 2 per thread
#pragma unroll
        for (int i = 0; i < 2; i++) {
            const int f4 = tid + i * 256;
            const int r = f4 >> 3, c = (f4 & 7) * 4;
            float4 v = *(const float4*)(W + (size_t)(col0 + r) * D_MODEL + k0 + c);
            Ws[r * GSTR + c + 0] = f2tf32(v.x);
            Ws[r * GSTR + c + 1] = f2tf32(v.y);
            Ws[r * GSTR + c + 2] = f2tf32(v.z);
            Ws[r * GSTR + c + 3] = f2tf32(v.w);
        }
        __syncthreads();

#pragma unroll
        for (int ks = 0; ks < 4; ks++) {
            const int kk = ks * 8;
            uint32_t a[2][4];
#pragma unroll
            for (int mi = 0; mi < 2; mi++) {
                const int rm = warp_m * 32 + mi * 16;
                a[mi][0] = __float_as_uint(As[(rm + g) * GSTR + kk + tg]);
                a[mi][1] = __float_as_uint(As[(rm + 8 + g) * GSTR + kk + tg]);
                a[mi][2] = __float_as_uint(As[(rm + g) * GSTR + kk + tg + 4]);
                a[mi][3] = __float_as_uint(As[(rm + 8 + g) * GSTR + kk + tg + 4]);
            }
#pragma unroll
            for (int ni = 0; ni < 4; ni++) {
                const int nb = warp_n * 32 + ni * 8;
                uint32_t b0 = __float_as_uint(Ws[(nb + g) * GSTR + kk + tg]);
                uint32_t b1 = __float_as_uint(Ws[(nb + g) * GSTR + kk + tg + 4]);
#pragma unroll
                for (int mi = 0; mi < 2; mi++)
                    mma_tf32(acc[mi][ni], a[mi][0], a[mi][1], a[mi][2], a[mi][3],
                             b0, b1);
            }
        }
    }

#pragma unroll
    for (int mi = 0; mi < 2; mi++) {
#pragma unroll
        for (int ni = 0; ni < 4; ni++) {
            const int r = row0 + warp_m * 32 + mi * 16 + g;
            const int c = col0 + warp_n * 32 + ni * 8 + 2 * tg;
            *(float2*)(C + (size_t)r * D_MODEL + c) =
                make_float2(acc[mi][ni][0], acc[mi][ni][1]);
            *(float2*)(C + (size_t)(r + 8) * D_MODEL + c) =
                make_float2(acc[mi][ni][2], acc[mi][ni][3]);
        }
    }
}

// ---------------------------------------------------------------------------
// Flash attention with tf32 mma. Br=Bc=64, 128 threads (4 warps),
// warp owns 16 q-rows. Causal kb <= qb. P round-trips through smem.
// ---------------------------------------------------------------------------
#define QSTR 68
#define VSTR 72
#define SMEM_ATTN ((64 * QSTR * 3 + 64 * VSTR) * 4)

__global__ __launch_bounds__(128) void attn_kernel(const float* __restrict__ Qg,
                                                   const float* __restrict__ Kg,
                                                   const float* __restrict__ Vg,
                                                   float* __restrict__ Og,
                                                   int SEQ) {
    extern __shared__ float sm[];
    float* Qs = sm;                    // [64][68] tf32
    float* Ks = Qs + 64 * QSTR;        // [64][68] tf32
    float* Ps = Ks + 64 * QSTR;        // [64][68] fp32 probs
    float* Vs = Ps + 64 * QSTR;        // [64][72] tf32

    const float inv_scale = 0.044194173824159216f;  // 1/sqrt(512)
    const int tid = threadIdx.x;
    const int lane = tid & 31, wid = tid >> 5;
    const int g = lane >> 2, tg = lane & 3;
    const int r0 = wid * 16;
    const int qb = gridDim.x - 1 - blockIdx.x;  // heavy tiles first
    const int bh = blockIdx.y;
    const int b = bh / NH, h = bh % NH;
    const size_t rowbase = (size_t)b * SEQ;
    const int colh = h * DH;

    // Load Q tile [64 x 64], tf32-rounded (8 float4 per thread)
#pragma unroll
    for (int i = 0; i < 8; i++) {
        const int f4 = tid + i * 128;
        const int r = f4 >> 4, c = (f4 & 15) * 4;
        float4 v = *(const float4*)(Qg + (rowbase + qb * 64 + r) * D_MODEL + colh + c);
        Qs[r * QSTR + c + 0] = f2tf32(v.x);
        Qs[r * QSTR + c + 1] = f2tf32(v.y);
        Qs[r * QSTR + c + 2] = f2tf32(v.z);
        Qs[r * QSTR + c + 3] = f2tf32(v.w);
    }

    float m[2] = {-1e30f, -1e30f}, l[2] = {0.f, 0.f};
    float oacc[8][4];
#pragma unroll
    for (int ni = 0; ni < 8; ni++)
#pragma unroll
        for (int c = 0; c < 4; c++) oacc[ni][c] = 0.f;

    for (int kb = 0; kb <= qb; kb++) {
        __syncthreads();
#pragma unroll
        for (int i = 0; i < 8; i++) {
            const int f4 = tid + i * 128;
            const int r = f4 >> 4, c = (f4 & 15) * 4;
            float4 kv = *(const float4*)(Kg + (rowbase + kb * 64 + r) * D_MODEL + colh + c);
            Ks[r * QSTR + c + 0] = f2tf32(kv.x);
            Ks[r * QSTR + c + 1] = f2tf32(kv.y);
            Ks[r * QSTR + c + 2] = f2tf32(kv.z);
            Ks[r * QSTR + c + 3] = f2tf32(kv.w);
            float4 vv = *(const float4*)(Vg + (rowbase + kb * 64 + r) * D_MODEL + colh + c);
            Vs[r * VSTR + c + 0] = f2tf32(vv.x);
            Vs[r * VSTR + c + 1] = f2tf32(vv.y);
            Vs[r * VSTR + c + 2] = f2tf32(vv.z);
            Vs[r * VSTR + c + 3] = f2tf32(vv.w);
        }
        __syncthreads();

        // S = Q K^T : warp computes rows r0..r0+15 x all 64 cols
        float sacc[8][4];
#pragma unroll
        for (int ni = 0; ni < 8; ni++)
#pragma unroll
            for (int c = 0; c < 4; c++) sacc[ni][c] = 0.f;

#pragma unroll
        for (int ks = 0; ks < 8; ks++) {
            const int kk = ks * 8;
            uint32_t a0 = __float_as_uint(Qs[(r0 + g) * QSTR + kk + tg]);
            uint32_t a1 = __float_as_uint(Qs[(r0 + 8 + g) * QSTR + kk + tg]);
            uint32_t a2 = __float_as_uint(Qs[(r0 + g) * QSTR + kk + tg + 4]);
            uint32_t a3 = __float_as_uint(Qs[(r0 + 8 + g) * QSTR + kk + tg + 4]);
#pragma unroll
            for (int ni = 0; ni < 8; ni++) {
                uint32_t b0 = __float_as_uint(Ks[(ni * 8 + g) * QSTR + kk + tg]);
                uint32_t b1 = __float_as_uint(Ks[(ni * 8 + g) * QSTR + kk + tg + 4]);
                mma_tf32(sacc[ni], a0, a1, a2, a3, b0, b1);
            }
        }

        // scale + causal mask (diagonal tile). (x-1e10)/scale underflows expf
        // to 0 exactly, same as -1e30 here.
        const bool diag = (kb == qb);
#pragma unroll
        for (int ni = 0; ni < 8; ni++)
#pragma unroll
            for (int c = 0; c < 4; c++) {
                const int j = ni * 8 + 2 * tg + (c & 1);
                const int r = r0 + g + (c >> 1) * 8;
                float sv = sacc[ni][c] * inv_scale;
                if (diag && j > r) sv = -1e30f;
                sacc[ni][c] = sv;
            }

        // online softmax per row-half i (i=0: row r0+g; i=1: row r0+8+g)
#pragma unroll
        for (int i = 0; i < 2; i++) {
            float rmax = -1e30f;
#pragma unroll
            for (int ni = 0; ni < 8; ni++)
                rmax = fmaxf(rmax, fmaxf(sacc[ni][i * 2], sacc[ni][i * 2 + 1]));
            rmax = fmaxf(rmax, __shfl_xor_sync(0xffffffffu, rmax, 1));
            rmax = fmaxf(rmax, __shfl_xor_sync(0xffffffffu, rmax, 2));
            const float mnew = fmaxf(m[i], rmax);
            const float corr = __expf(m[i] - mnew);
            float rsum = 0.f;
#pragma unroll
            for (int ni = 0; ni < 8; ni++) {
                float p0 = __expf(sacc[ni][i * 2] - mnew);
                float p1 = __expf(sacc[ni][i * 2 + 1] - mnew);
                sacc[ni][i * 2] = p0;
                sacc[ni][i * 2 + 1] = p1;
                rsum += p0 + p1;
            }
            rsum += __shfl_xor_sync(0xffffffffu, rsum, 1);
            rsum += __shfl_xor_sync(0xffffffffu, rsum, 2);
            l[i] = l[i] * corr + rsum;
            m[i] = mnew;
#pragma unroll
            for (int ni = 0; ni < 8; ni++) {
                oacc[ni][i * 2] *= corr;
                oacc[ni][i * 2 + 1] *= corr;
            }
        }

        // P (warp-private rows) -> smem for A-fragment reload
#pragma unroll
        for (int ni = 0; ni < 8; ni++) {
            Ps[(r0 + g) * QSTR + ni * 8 + 2 * tg] = sacc[ni][0];
            Ps[(r0 + g) * QSTR + ni * 8 + 2 * tg + 1] = sacc[ni][1];
            Ps[(r0 + 8 + g) * QSTR + ni * 8 + 2 * tg] = sacc[ni][2];
            Ps[(r0 + 8 + g) * QSTR + ni * 8 + 2 * tg + 1] = sacc[ni][3];
        }
        __syncwarp();

        // O += P V
#pragma unroll
        for (int ks = 0; ks < 8; ks++) {
            const int j0 = ks * 8;
            uint32_t a0 = __float_as_uint(f2tf32(Ps[(r0 + g) * QSTR + j0 + tg]));
            uint32_t a1 = __float_as_uint(f2tf32(Ps[(r0 + 8 + g) * QSTR + j0 + tg]));
            uint32_t a2 = __float_as_uint(f2tf32(Ps[(r0 + g) * QSTR + j0 + tg + 4]));
            uint32_t a3 = __float_as_uint(f2tf32(Ps[(r0 + 8 + g) * QSTR + j0 + tg + 4]));
#pragma unroll
            for (int ni = 0; ni < 8; ni++) {
                uint32_t b0 = __float_as_uint(Vs[(j0 + tg) * VSTR + ni * 8 + g]);
                uint32_t b1 = __float_as_uint(Vs[(j0 + tg + 4) * VSTR + ni * 8 + g]);
                mma_tf32(oacc[ni], a0, a1, a2, a3, b0, b1);
            }
        }
    }

    const float inv0 = 1.f / l[0], inv1 = 1.f / l[1];
#pragma unroll
    for (int ni = 0; ni < 8; ni++) {
        const size_t rA = rowbase + qb * 64 + r0 + g;
        const int c = colh + ni * 8 + 2 * tg;
        *(float2*)(Og + rA * D_MODEL + c) =
            make_float2(oacc[ni][0] * inv0, oacc[ni][1] * inv0);
        *(float2*)(Og + (rA + 8) * D_MODEL + c) =
            make_float2(oacc[ni][2] * inv1, oacc[ni][3] * inv1);
    }
}

// ---------------------------------------------------------------------------
extern "C" void kernel_launch(void* const* d_in, const int* in_sizes, int n_in,
                              void* d_out, int out_size) {
    const float* q  = (const float*)d_in[0];
    const float* k  = (const float*)d_in[1];
    const float* v  = (const float*)d_in[2];
    const float* wq = (const float*)d_in[3];
    const float* wk = (const float*)d_in[4];
    const float* wv = (const float*)d_in[5];
    const float* wo = (const float*)d_in[6];
    float* out = (float*)d_out;

    const int M = in_sizes[0] / D_MODEL;  // B*S = 4096
    const int B = 2;
    const int SEQ = M / B;                // 2048

    float *gq, *gk, *gv, *ga;
    cudaGetSymbolAddress((void**)&gq, g_q);
    cudaGetSymbolAddress((void**)&gk, g_k);
    cudaGetSymbolAddress((void**)&gv, g_v);
    cudaGetSymbolAddress((void**)&ga, g_att);

    cudaFuncSetAttribute(attn_kernel,
                         cudaFuncAttributeMaxDynamicSharedMemorySize,
                         SMEM_ATTN);

    dim3 gg(M / 128, D_MODEL / 64);
    gemm_xwT<<<gg, 256>>>(q, wq, gq);
    gemm_xwT<<<gg, 256>>>(k, wk, gk);
    gemm_xwT<<<gg, 256>>>(v, wv, gv);

    dim3 ag(SEQ / 64, B * NH);
    attn_kernel<<<ag, 128, SMEM_ATTN>>>(gq, gk, gv, ga, SEQ);

    gemm_xwT<<<gg, 256>>>(ga, wo, out);
}

// round 4
// speedup vs baseline: 3.3234x; 1.0692x over previous
#include <cuda_runtime.h>
#include <cstdint>

#define D_MODEL 512
#define NH 8
#define DH 64

// Scratch (allocation-free rule: __device__ globals). 4 x 8MB.
__device__ float g_q[4096 * 512];
__device__ float g_k[4096 * 512];
__device__ float g_v[4096 * 512];
__device__ float g_att[4096 * 512];

__device__ __forceinline__ float f2tf32(float x) {
    uint32_t y;
    asm("cvt.rna.tf32.f32 %0, %1;" : "=r"(y) : "f"(x));
    return __uint_as_float(y);
}

__device__ __forceinline__ void mma_tf32(float* c, uint32_t a0, uint32_t a1,
                                         uint32_t a2, uint32_t a3, uint32_t b0,
                                         uint32_t b1) {
    asm volatile(
        "mma.sync.aligned.m16n8k8.row.col.f32.tf32.tf32.f32 "
        "{%0,%1,%2,%3}, {%4,%5,%6,%7}, {%8,%9}, {%0,%1,%2,%3};"
        : "+f"(c[0]), "+f"(c[1]), "+f"(c[2]), "+f"(c[3])
        : "r"(a0), "r"(a1), "r"(a2), "r"(a3), "r"(b0), "r"(b1));
}

__device__ __forceinline__ void cp_async16(void* smem_dst, const void* gmem_src) {
    uint32_t s = (uint32_t)__cvta_generic_to_shared(smem_dst);
    asm volatile("cp.async.cg.shared.global [%0], [%1], 16;\n" ::"r"(s),
                 "l"(gmem_src));
}
#define CP_COMMIT() asm volatile("cp.async.commit_group;\n" ::: "memory")
#define CP_WAIT0() asm volatile("cp.async.wait_group 0;\n" ::: "memory")

// ---------------------------------------------------------------------------
// C[M,512] = A[M,512] @ W[512,512]^T  via tf32 mma, cp.async 2-stage pipeline.
// BM=128, BN=128, BK=32. 256 threads = 8 warps (2 m x 4 n), warp tile 64x32.
// RNA tf32 rounding applied at fragment load (numerically == rounding before
// smem store). If ROUND_OUT, the fp32 result is tf32-rounded before store so
// downstream consumers need no cvt.
// ---------------------------------------------------------------------------
#define GSTR 36
#define SMEM_GEMM (2 * 2 * 128 * GSTR * 4)  // 2 stages x (A+B) x 128 x 36 floats

template <int ROUND_OUT>
__global__ void __launch_bounds__(256, 2)
    gemm_xwT(const float* __restrict__ A, const float* __restrict__ W,
             float* __restrict__ C) {
    extern __shared__ float smg[];
    float* As = smg;                    // [2][128][GSTR]
    float* Ws = smg + 2 * 128 * GSTR;   // [2][128][GSTR]

    const int tid = threadIdx.x;
    const int lane = tid & 31, wid = tid >> 5;
    const int g = lane >> 2, tg = lane & 3;
    const int warp_m = wid >> 2, warp_n = wid & 3;  // 2 x 4
    const int row0 = blockIdx.x * 128, col0 = blockIdx.y * 128;

    float acc[4][4][4];
#pragma unroll
    for (int mi = 0; mi < 4; mi++)
#pragma unroll
        for (int ni = 0; ni < 4; ni++)
#pragma unroll
            for (int c = 0; c < 4; c++) acc[mi][ni][c] = 0.f;

    auto load_stage = [&](int k0, int st) {
        float* Ad = As + st * 128 * GSTR;
        float* Wd = Ws + st * 128 * GSTR;
#pragma unroll
        for (int i = 0; i < 4; i++) {
            const int f4 = tid + i * 256;
            const int r = f4 >> 3, c = (f4 & 7) * 4;
            cp_async16(Ad + r * GSTR + c, A + (size_t)(row0 + r) * D_MODEL + k0 + c);
            cp_async16(Wd + r * GSTR + c, W + (size_t)(col0 + r) * D_MODEL + k0 + c);
        }
        CP_COMMIT();
    };

    load_stage(0, 0);

    for (int it = 0; it < D_MODEL / 32; it++) {
        CP_WAIT0();
        __syncthreads();
        if (it + 1 < D_MODEL / 32) load_stage((it + 1) * 32, (it + 1) & 1);

        const float* Ab = As + (it & 1) * 128 * GSTR;
        const float* Wb = Ws + (it & 1) * 128 * GSTR;
#pragma unroll
        for (int ks = 0; ks < 4; ks++) {
            const int kk = ks * 8;
            uint32_t a[4][4];
#pragma unroll
            for (int mi = 0; mi < 4; mi++) {
                const int rm = warp_m * 64 + mi * 16;
                a[mi][0] = __float_as_uint(f2tf32(Ab[(rm + g) * GSTR + kk + tg]));
                a[mi][1] = __float_as_uint(f2tf32(Ab[(rm + 8 + g) * GSTR + kk + tg]));
                a[mi][2] = __float_as_uint(f2tf32(Ab[(rm + g) * GSTR + kk + tg + 4]));
                a[mi][3] = __float_as_uint(f2tf32(Ab[(rm + 8 + g) * GSTR + kk + tg + 4]));
            }
#pragma unroll
            for (int ni = 0; ni < 4; ni++) {
                const int nb = warp_n * 32 + ni * 8;
                uint32_t b0 = __float_as_uint(f2tf32(Wb[(nb + g) * GSTR + kk + tg]));
                uint32_t b1 = __float_as_uint(f2tf32(Wb[(nb + g) * GSTR + kk + tg + 4]));
#pragma unroll
                for (int mi = 0; mi < 4; mi++)
                    mma_tf32(acc[mi][ni], a[mi][0], a[mi][1], a[mi][2], a[mi][3],
                             b0, b1);
            }
        }
    }

#pragma unroll
    for (int mi = 0; mi < 4; mi++) {
#pragma unroll
        for (int ni = 0; ni < 4; ni++) {
            const int r = row0 + warp_m * 64 + mi * 16 + g;
            const int c = col0 + warp_n * 32 + ni * 8 + 2 * tg;
            float v0 = acc[mi][ni][0], v1 = acc[mi][ni][1];
            float v2 = acc[mi][ni][2], v3 = acc[mi][ni][3];
            if (ROUND_OUT) {
                v0 = f2tf32(v0); v1 = f2tf32(v1);
                v2 = f2tf32(v2); v3 = f2tf32(v3);
            }
            *(float2*)(C + (size_t)r * D_MODEL + c) = make_float2(v0, v1);
            *(float2*)(C + (size_t)(r + 8) * D_MODEL + c) = make_float2(v2, v3);
        }
    }
}

// ---------------------------------------------------------------------------
// Flash attention, tf32 mma, Br=128, Bc=64, 256 threads (8 warps x 16 rows).
// Inputs pre-rounded to tf32 by the projection GEMMs, so K/V stream in raw
// via cp.async (2-stage double buffer). P never touches smem: the C-fragment
// -> A-fragment relayout is done with intra-quad shuffles.
// ---------------------------------------------------------------------------
#define QSTR 68
#define VSTR 72
#define SMEM_ATTN ((128 * QSTR + 2 * 64 * QSTR + 2 * 64 * VSTR) * 4)

__global__ void __launch_bounds__(256, 2)
    attn_kernel(const float* __restrict__ Qg, const float* __restrict__ Kg,
                const float* __restrict__ Vg, float* __restrict__ Og, int SEQ) {
    extern __shared__ float sm[];
    float* Qs = sm;                         // [128][QSTR]
    float* Ks = sm + 128 * QSTR;            // [2][64][QSTR]
    float* Vs = Ks + 2 * 64 * QSTR;         // [2][64][VSTR]

    const float inv_scale = 0.044194173824159216f;  // 1/sqrt(512)
    const int tid = threadIdx.x;
    const int lane = tid & 31, wid = tid >> 5;
    const int g = lane >> 2, tg = lane & 3;
    const int r0 = wid * 16;                // warp's 16 q-rows within tile
    const int qb = gridDim.x - 1 - blockIdx.x;  // heavy tiles first
    const int bh = blockIdx.y;
    const int b = bh / NH, h = bh % NH;
    const size_t rowbase = (size_t)b * SEQ;
    const int colh = h * DH;
    const int kbmax = 2 * qb + 1;

    auto load_kv = [&](int kb, int st) {
        const float* Kb = Kg + (rowbase + kb * 64) * D_MODEL + colh;
        const float* Vb = Vg + (rowbase + kb * 64) * D_MODEL + colh;
        float* Kd = Ks + st * 64 * QSTR;
        float* Vd = Vs + st * 64 * VSTR;
#pragma unroll
        for (int i = 0; i < 4; i++) {
            const int f4 = tid + i * 256;
            const int r = f4 >> 4, c = (f4 & 15) * 4;
            cp_async16(Kd + r * QSTR + c, Kb + (size_t)r * D_MODEL + c);
            cp_async16(Vd + r * VSTR + c, Vb + (size_t)r * D_MODEL + c);
        }
        CP_COMMIT();
    };

    load_kv(0, 0);

    // Q tile [128 x 64] (pre-rounded tf32): plain loads overlap the cp.async
#pragma unroll
    for (int i = 0; i < 8; i++) {
        const int f4 = tid + i * 256;
        const int r = f4 >> 4, c = (f4 & 15) * 4;
        float4 v = *(const float4*)(Qg + (rowbase + qb * 128 + r) * D_MODEL + colh + c);
        Qs[r * QSTR + c + 0] = v.x; Qs[r * QSTR + c + 1] = v.y;
        Qs[r * QSTR + c + 2] = v.z; Qs[r * QSTR + c + 3] = v.w;
    }

    float m[2] = {-1e30f, -1e30f}, l[2] = {0.f, 0.f};
    float oacc[8][4];
#pragma unroll
    for (int ni = 0; ni < 8; ni++)
#pragma unroll
        for (int c = 0; c < 4; c++) oacc[ni][c] = 0.f;

    for (int kb = 0; kb <= kbmax; kb++) {
        CP_WAIT0();
        __syncthreads();
        if (kb + 1 <= kbmax) load_kv(kb + 1, (kb + 1) & 1);

        const float* Kb = Ks + (kb & 1) * 64 * QSTR;
        const float* Vb = Vs + (kb & 1) * 64 * VSTR;

        // causal geometry (warp-uniform): key cols kb*64+j vs q rows qb*128+r
        const int joff = kb * 64 - qb * 128;
        if (joff > r0 + 15) continue;           // warp fully masked
        const bool need_mask = (joff + 63 > r0);

        // S = Q K^T
        float sacc[8][4];
#pragma unroll
        for (int ni = 0; ni < 8; ni++)
#pragma unroll
            for (int c = 0; c < 4; c++) sacc[ni][c] = 0.f;

#pragma unroll
        for (int ks = 0; ks < 8; ks++) {
            const int kk = ks * 8;
            uint32_t a0 = __float_as_uint(Qs[(r0 + g) * QSTR + kk + tg]);
            uint32_t a1 = __float_as_uint(Qs[(r0 + 8 + g) * QSTR + kk + tg]);
            uint32_t a2 = __float_as_uint(Qs[(r0 + g) * QSTR + kk + tg + 4]);
            uint32_t a3 = __float_as_uint(Qs[(r0 + 8 + g) * QSTR + kk + tg + 4]);
#pragma unroll
            for (int ni = 0; ni < 8; ni++) {
                uint32_t b0 = __float_as_uint(Kb[(ni * 8 + g) * QSTR + kk + tg]);
                uint32_t b1 = __float_as_uint(Kb[(ni * 8 + g) * QSTR + kk + tg + 4]);
                mma_tf32(sacc[ni], a0, a1, a2, a3, b0, b1);
            }
        }

        // scale + causal mask. Reference's (x-1e10)/scale underflows expf to 0,
        // identical to -1e30 here.
#pragma unroll
        for (int ni = 0; ni < 8; ni++)
#pragma unroll
            for (int c = 0; c < 4; c++) {
                float sv = sacc[ni][c] * inv_scale;
                if (need_mask) {
                    const int j = joff + ni * 8 + 2 * tg + (c & 1);
                    const int r = r0 + g + (c >> 1) * 8;
                    if (j > r) sv = -1e30f;
                }
                sacc[ni][c] = sv;
            }

        // online softmax per row-half (i=0: row r0+g; i=1: row r0+8+g)
#pragma unroll
        for (int i = 0; i < 2; i++) {
            float rmax = -1e30f;
#pragma unroll
            for (int ni = 0; ni < 8; ni++)
                rmax = fmaxf(rmax, fmaxf(sacc[ni][i * 2], sacc[ni][i * 2 + 1]));
            rmax = fmaxf(rmax, __shfl_xor_sync(0xffffffffu, rmax, 1));
            rmax = fmaxf(rmax, __shfl_xor_sync(0xffffffffu, rmax, 2));
            const float mnew = fmaxf(m[i], rmax);
            const float corr = __expf(m[i] - mnew);
            float rsum = 0.f;
#pragma unroll
            for (int ni = 0; ni < 8; ni++) {
                float p0 = __expf(sacc[ni][i * 2] - mnew);
                float p1 = __expf(sacc[ni][i * 2 + 1] - mnew);
                sacc[ni][i * 2] = p0;
                sacc[ni][i * 2 + 1] = p1;
                rsum += p0 + p1;
            }
            rsum += __shfl_xor_sync(0xffffffffu, rsum, 1);
            rsum += __shfl_xor_sync(0xffffffffu, rsum, 2);
            l[i] = l[i] * corr + rsum;
            m[i] = mnew;
#pragma unroll
            for (int ni = 0; ni < 8; ni++) {
                oacc[ni][i * 2] *= corr;
                oacc[ni][i * 2 + 1] *= corr;
            }
        }

        // O += P V. C-fragment -> A-fragment via intra-quad shuffles:
        // a0 = P(r0+g, 8ks+tg) etc. Source lane tg' = tg>>1 (+2 for +4 cols),
        // element parity = tg&1.
        const int src0 = (lane & ~3) | (tg >> 1);
        const bool odd = tg & 1;
#pragma unroll
        for (int ks = 0; ks < 8; ks++) {
            float p00 = __shfl_sync(0xffffffffu, sacc[ks][0], src0);
            float p01 = __shfl_sync(0xffffffffu, sacc[ks][1], src0);
            float p10 = __shfl_sync(0xffffffffu, sacc[ks][2], src0);
            float p11 = __shfl_sync(0xffffffffu, sacc[ks][3], src0);
            float q00 = __shfl_sync(0xffffffffu, sacc[ks][0], src0 + 2);
            float q01 = __shfl_sync(0xffffffffu, sacc[ks][1], src0 + 2);
            float q10 = __shfl_sync(0xffffffffu, sacc[ks][2], src0 + 2);
            float q11 = __shfl_sync(0xffffffffu, sacc[ks][3], src0 + 2);
            uint32_t a0 = __float_as_uint(f2tf32(odd ? p01 : p00));
            uint32_t a1 = __float_as_uint(f2tf32(odd ? p11 : p10));
            uint32_t a2 = __float_as_uint(f2tf32(odd ? q01 : q00));
            uint32_t a3 = __float_as_uint(f2tf32(odd ? q11 : q10));
            const int j0 = ks * 8;
#pragma unroll
            for (int ni = 0; ni < 8; ni++) {
                uint32_t b0 = __float_as_uint(Vb[(j0 + tg) * VSTR + ni * 8 + g]);
                uint32_t b1 = __float_as_uint(Vb[(j0 + tg + 4) * VSTR + ni * 8 + g]);
                mma_tf32(oacc[ni], a0, a1, a2, a3, b0, b1);
            }
        }
    }

    const float inv0 = 1.f / l[0], inv1 = 1.f / l[1];
#pragma unroll
    for (int ni = 0; ni < 8; ni++) {
        const size_t rA = rowbase + qb * 128 + r0 + g;
        const int c = colh + ni * 8 + 2 * tg;
        *(float2*)(Og + rA * D_MODEL + c) =
            make_float2(oacc[ni][0] * inv0, oacc[ni][1] * inv0);
        *(float2*)(Og + (rA + 8) * D_MODEL + c) =
            make_float2(oacc[ni][2] * inv1, oacc[ni][3] * inv1);
    }
}

// ---------------------------------------------------------------------------
extern "C" void kernel_launch(void* const* d_in, const int* in_sizes, int n_in,
                              void* d_out, int out_size) {
    const float* q  = (const float*)d_in[0];
    const float* k  = (const float*)d_in[1];
    const float* v  = (const float*)d_in[2];
    const float* wq = (const float*)d_in[3];
    const float* wk = (const float*)d_in[4];
    const float* wv = (const float*)d_in[5];
    const float* wo = (const float*)d_in[6];
    float* out = (float*)d_out;

    const int M = in_sizes[0] / D_MODEL;  // B*S = 4096
    const int B = 2;
    const int SEQ = M / B;                // 2048

    float *gq, *gk, *gv, *ga;
    cudaGetSymbolAddress((void**)&gq, g_q);
    cudaGetSymbolAddress((void**)&gk, g_k);
    cudaGetSymbolAddress((void**)&gv, g_v);
    cudaGetSymbolAddress((void**)&ga, g_att);

    cudaFuncSetAttribute(gemm_xwT<1>, cudaFuncAttributeMaxDynamicSharedMemorySize,
                         SMEM_GEMM);
    cudaFuncSetAttribute(gemm_xwT<0>, cudaFuncAttributeMaxDynamicSharedMemorySize,
                         SMEM_GEMM);
    cudaFuncSetAttribute(attn_kernel, cudaFuncAttributeMaxDynamicSharedMemorySize,
                         SMEM_ATTN);

    dim3 gg(M / 128, D_MODEL / 128);
    gemm_xwT<1><<<gg, 256, SMEM_GEMM>>>(q, wq, gq);
    gemm_xwT<1><<<gg, 256, SMEM_GEMM>>>(k, wk, gk);
    gemm_xwT<1><<<gg, 256, SMEM_GEMM>>>(v, wv, gv);

    dim3 ag(SEQ / 128, B * NH);
    attn_kernel<<<ag, 256, SMEM_ATTN>>>(gq, gk, gv, ga, SEQ);

    gemm_xwT<0><<<gg, 256, SMEM_GEMM>>>(ga, wo, out);
}

// round 5
// speedup vs baseline: 4.2663x; 1.2837x over previous
#include <cuda_runtime.h>
#include <cstdint>

#define D_MODEL 512
#define NH 8
#define DH 64

// Scratch (allocation-free rule: __device__ globals).
__device__ float g_q[4096 * 512];
__device__ float g_k[4096 * 512];
__device__ float g_v[4096 * 512];
__device__ float g_att[4096 * 512];
// Split-KV partials: up to 4 chunks per q-row.
__device__ float g_op[4 * 4096 * 512];
__device__ float g_m[4 * 8 * 4096];
__device__ float g_l[4 * 8 * 4096];

// Work-item table: 40 items per bh -> (qb, chunk). nchunks(qb) = qb/4 + 1.
__constant__ unsigned char c_qb[40] = {
    0, 1, 2, 3, 4, 4, 5, 5, 6, 6, 7, 7, 8, 8, 8, 9, 9, 9, 10, 10,
    10, 11, 11, 11, 12, 12, 12, 12, 13, 13, 13, 13, 14, 14, 14, 14, 15, 15, 15, 15};
__constant__ unsigned char c_ch[40] = {
    0, 0, 0, 0, 0, 1, 0, 1, 0, 1, 0, 1, 0, 1, 2, 0, 1, 2, 0, 1,
    2, 0, 1, 2, 0, 1, 2, 3, 0, 1, 2, 3, 0, 1, 2, 3, 0, 1, 2, 3};

__device__ __forceinline__ float f2tf32(float x) {
    uint32_t y;
    asm("cvt.rna.tf32.f32 %0, %1;" : "=r"(y) : "f"(x));
    return __uint_as_float(y);
}

__device__ __forceinline__ void mma_tf32(float* c, uint32_t a0, uint32_t a1,
                                         uint32_t a2, uint32_t a3, uint32_t b0,
                                         uint32_t b1) {
    asm volatile(
        "mma.sync.aligned.m16n8k8.row.col.f32.tf32.tf32.f32 "
        "{%0,%1,%2,%3}, {%4,%5,%6,%7}, {%8,%9}, {%0,%1,%2,%3};"
        : "+f"(c[0]), "+f"(c[1]), "+f"(c[2]), "+f"(c[3])
        : "r"(a0), "r"(a1), "r"(a2), "r"(a3), "r"(b0), "r"(b1));
}

__device__ __forceinline__ void cp_async16(void* smem_dst, const void* gmem_src) {
    uint32_t s = (uint32_t)__cvta_generic_to_shared(smem_dst);
    asm volatile("cp.async.cg.shared.global [%0], [%1], 16;\n" ::"r"(s),
                 "l"(gmem_src));
}
#define CP_COMMIT() asm volatile("cp.async.commit_group;\n" ::: "memory")
#define CP_WAIT0() asm volatile("cp.async.wait_group 0;\n" ::: "memory")

// ---------------------------------------------------------------------------
// C[M,512] = A[M,512] @ W[512,512]^T  via tf32 mma, cp.async 2-stage pipeline.
// BM=128, BN=128, BK=32. 256 threads = 8 warps (2m x 4n), warp tile 64x32.
// blockIdx.z selects one of up to 3 independent (A, W, C) triples so the
// projection phase fills the chip with one launch.
// ---------------------------------------------------------------------------
#define GSTR 36
#define SMEM_GEMM (2 * 2 * 128 * GSTR * 4)

template <int ROUND_OUT>
__global__ void __launch_bounds__(256, 2)
    gemm_xwT(const float* __restrict__ A0, const float* __restrict__ W0,
             float* __restrict__ C0, const float* __restrict__ A1,
             const float* __restrict__ W1, float* __restrict__ C1,
             const float* __restrict__ A2, const float* __restrict__ W2,
             float* __restrict__ C2) {
    extern __shared__ float smg[];
    float* As = smg;                    // [2][128][GSTR]
    float* Ws = smg + 2 * 128 * GSTR;   // [2][128][GSTR]

    const int z = blockIdx.z;
    const float* A = (z == 0) ? A0 : (z == 1) ? A1 : A2;
    const float* W = (z == 0) ? W0 : (z == 1) ? W1 : W2;
    float* C = (z == 0) ? C0 : (z == 1) ? C1 : C2;

    const int tid = threadIdx.x;
    const int lane = tid & 31, wid = tid >> 5;
    const int g = lane >> 2, tg = lane & 3;
    const int warp_m = wid >> 2, warp_n = wid & 3;
    const int row0 = blockIdx.x * 128, col0 = blockIdx.y * 128;

    float acc[4][4][4];
#pragma unroll
    for (int mi = 0; mi < 4; mi++)
#pragma unroll
        for (int ni = 0; ni < 4; ni++)
#pragma unroll
            for (int c = 0; c < 4; c++) acc[mi][ni][c] = 0.f;

    auto load_stage = [&](int k0, int st) {
        float* Ad = As + st * 128 * GSTR;
        float* Wd = Ws + st * 128 * GSTR;
#pragma unroll
        for (int i = 0; i < 4; i++) {
            const int f4 = tid + i * 256;
            const int r = f4 >> 3, c = (f4 & 7) * 4;
            cp_async16(Ad + r * GSTR + c, A + (size_t)(row0 + r) * D_MODEL + k0 + c);
            cp_async16(Wd + r * GSTR + c, W + (size_t)(col0 + r) * D_MODEL + k0 + c);
        }
        CP_COMMIT();
    };

    load_stage(0, 0);

    for (int it = 0; it < D_MODEL / 32; it++) {
        CP_WAIT0();
        __syncthreads();
        if (it + 1 < D_MODEL / 32) load_stage((it + 1) * 32, (it + 1) & 1);

        const float* Ab = As + (it & 1) * 128 * GSTR;
        const float* Wb = Ws + (it & 1) * 128 * GSTR;
#pragma unroll
        for (int ks = 0; ks < 4; ks++) {
            const int kk = ks * 8;
            uint32_t a[4][4];
#pragma unroll
            for (int mi = 0; mi < 4; mi++) {
                const int rm = warp_m * 64 + mi * 16;
                a[mi][0] = __float_as_uint(f2tf32(Ab[(rm + g) * GSTR + kk + tg]));
                a[mi][1] = __float_as_uint(f2tf32(Ab[(rm + 8 + g) * GSTR + kk + tg]));
                a[mi][2] = __float_as_uint(f2tf32(Ab[(rm + g) * GSTR + kk + tg + 4]));
                a[mi][3] = __float_as_uint(f2tf32(Ab[(rm + 8 + g) * GSTR + kk + tg + 4]));
            }
#pragma unroll
            for (int ni = 0; ni < 4; ni++) {
                const int nb = warp_n * 32 + ni * 8;
                uint32_t b0 = __float_as_uint(f2tf32(Wb[(nb + g) * GSTR + kk + tg]));
                uint32_t b1 = __float_as_uint(f2tf32(Wb[(nb + g) * GSTR + kk + tg + 4]));
#pragma unroll
                for (int mi = 0; mi < 4; mi++)
                    mma_tf32(acc[mi][ni], a[mi][0], a[mi][1], a[mi][2], a[mi][3],
                             b0, b1);
            }
        }
    }

#pragma unroll
    for (int mi = 0; mi < 4; mi++) {
#pragma unroll
        for (int ni = 0; ni < 4; ni++) {
            const int r = row0 + warp_m * 64 + mi * 16 + g;
            const int c = col0 + warp_n * 32 + ni * 8 + 2 * tg;
            float v0 = acc[mi][ni][0], v1 = acc[mi][ni][1];
            float v2 = acc[mi][ni][2], v3 = acc[mi][ni][3];
            if (ROUND_OUT) {
                v0 = f2tf32(v0); v1 = f2tf32(v1);
                v2 = f2tf32(v2); v3 = f2tf32(v3);
            }
            *(float2*)(C + (size_t)r * D_MODEL + c) = make_float2(v0, v1);
            *(float2*)(C + (size_t)(r + 8) * D_MODEL + c) = make_float2(v2, v3);
        }
    }
}

// ---------------------------------------------------------------------------
// Split-KV flash attention, tf32 mma. Br=128, Bc=64, 256 threads (8 warps x
// 16 rows). Each block: one (bh, q-tile, 8-iteration KV chunk) -> writes
// UNNORMALIZED O partial + per-row (m, l). Inputs pre-rounded tf32.
// ---------------------------------------------------------------------------
#define QSTR 68
#define VSTR 72
#define SMEM_ATTN ((128 * QSTR + 2 * 64 * QSTR + 2 * 64 * VSTR) * 4)

__global__ void __launch_bounds__(256, 2)
    attn_kernel(const float* __restrict__ Qg, const float* __restrict__ Kg,
                const float* __restrict__ Vg, float* __restrict__ Op,
                float* __restrict__ Mp, float* __restrict__ Lp, int SEQ) {
    extern __shared__ float sm[];
    float* Qs = sm;                         // [128][QSTR]
    float* Ks = sm + 128 * QSTR;            // [2][64][QSTR]
    float* Vs = Ks + 2 * 64 * QSTR;         // [2][64][VSTR]

    const float inv_scale = 0.044194173824159216f;  // 1/sqrt(512)
    const int tid = threadIdx.x;
    const int lane = tid & 31, wid = tid >> 5;
    const int g = lane >> 2, tg = lane & 3;
    const int r0 = wid * 16;
    const int bh = blockIdx.x / 40;
    const int item = blockIdx.x % 40;
    const int qb = c_qb[item];
    const int ch = c_ch[item];
    const int b = bh >> 3, h = bh & 7;
    const size_t rowbase = (size_t)b * SEQ;
    const int colh = h * DH;
    const int kbmax = 2 * qb + 1;
    const int kb0 = ch * 8;
    const int kbe = min(kb0 + 7, kbmax);

    auto load_kv = [&](int kb, int st) {
        const float* Kb = Kg + (rowbase + kb * 64) * D_MODEL + colh;
        const float* Vb = Vg + (rowbase + kb * 64) * D_MODEL + colh;
        float* Kd = Ks + st * 64 * QSTR;
        float* Vd = Vs + st * 64 * VSTR;
#pragma unroll
        for (int i = 0; i < 4; i++) {
            const int f4 = tid + i * 256;
            const int r = f4 >> 4, c = (f4 & 15) * 4;
            cp_async16(Kd + r * QSTR + c, Kb + (size_t)r * D_MODEL + c);
            cp_async16(Vd + r * VSTR + c, Vb + (size_t)r * D_MODEL + c);
        }
        CP_COMMIT();
    };

    load_kv(kb0, kb0 & 1);

    // Q tile [128 x 64] (pre-rounded tf32)
#pragma unroll
    for (int i = 0; i < 8; i++) {
        const int f4 = tid + i * 256;
        const int r = f4 >> 4, c = (f4 & 15) * 4;
        float4 v = *(const float4*)(Qg + (rowbase + qb * 128 + r) * D_MODEL + colh + c);
        Qs[r * QSTR + c + 0] = v.x; Qs[r * QSTR + c + 1] = v.y;
        Qs[r * QSTR + c + 2] = v.z; Qs[r * QSTR + c + 3] = v.w;
    }

    float m[2] = {-1e30f, -1e30f}, l[2] = {0.f, 0.f};
    float oacc[8][4];
#pragma unroll
    for (int ni = 0; ni < 8; ni++)
#pragma unroll
        for (int c = 0; c < 4; c++) oacc[ni][c] = 0.f;

    for (int kb = kb0; kb <= kbe; kb++) {
        CP_WAIT0();
        __syncthreads();
        if (kb + 1 <= kbe) load_kv(kb + 1, (kb + 1) & 1);

        const float* Kb = Ks + (kb & 1) * 64 * QSTR;
        const float* Vb = Vs + (kb & 1) * 64 * VSTR;

        const int joff = kb * 64 - qb * 128;
        if (joff > r0 + 15) continue;           // warp fully masked
        const bool need_mask = (joff + 63 > r0);

        float sacc[8][4];
#pragma unroll
        for (int ni = 0; ni < 8; ni++)
#pragma unroll
            for (int c = 0; c < 4; c++) sacc[ni][c] = 0.f;

#pragma unroll
        for (int ks = 0; ks < 8; ks++) {
            const int kk = ks * 8;
            uint32_t a0 = __float_as_uint(Qs[(r0 + g) * QSTR + kk + tg]);
            uint32_t a1 = __float_as_uint(Qs[(r0 + 8 + g) * QSTR + kk + tg]);
            uint32_t a2 = __float_as_uint(Qs[(r0 + g) * QSTR + kk + tg + 4]);
            uint32_t a3 = __float_as_uint(Qs[(r0 + 8 + g) * QSTR + kk + tg + 4]);
#pragma unroll
            for (int ni = 0; ni < 8; ni++) {
                uint32_t b0 = __float_as_uint(Kb[(ni * 8 + g) * QSTR + kk + tg]);
                uint32_t b1 = __float_as_uint(Kb[(ni * 8 + g) * QSTR + kk + tg + 4]);
                mma_tf32(sacc[ni], a0, a1, a2, a3, b0, b1);
            }
        }

        // scale + causal mask ((x-1e10)/scale underflows expf to 0 == -1e30)
#pragma unroll
        for (int ni = 0; ni < 8; ni++)
#pragma unroll
            for (int c = 0; c < 4; c++) {
                float sv = sacc[ni][c] * inv_scale;
                if (need_mask) {
                    const int j = joff + ni * 8 + 2 * tg + (c & 1);
                    const int r = r0 + g + (c >> 1) * 8;
                    if (j > r) sv = -1e30f;
                }
                sacc[ni][c] = sv;
            }

        // online softmax per row-half
#pragma unroll
        for (int i = 0; i < 2; i++) {
            float rmax = -1e30f;
#pragma unroll
            for (int ni = 0; ni < 8; ni++)
                rmax = fmaxf(rmax, fmaxf(sacc[ni][i * 2], sacc[ni][i * 2 + 1]));
            rmax = fmaxf(rmax, __shfl_xor_sync(0xffffffffu, rmax, 1));
            rmax = fmaxf(rmax, __shfl_xor_sync(0xffffffffu, rmax, 2));
            const float mnew = fmaxf(m[i], rmax);
            const float corr = __expf(m[i] - mnew);
            float rsum = 0.f;
#pragma unroll
            for (int ni = 0; ni < 8; ni++) {
                float p0 = __expf(sacc[ni][i * 2] - mnew);
                float p1 = __expf(sacc[ni][i * 2 + 1] - mnew);
                sacc[ni][i * 2] = p0;
                sacc[ni][i * 2 + 1] = p1;
                rsum += p0 + p1;
            }
            rsum += __shfl_xor_sync(0xffffffffu, rsum, 1);
            rsum += __shfl_xor_sync(0xffffffffu, rsum, 2);
            l[i] = l[i] * corr + rsum;
            m[i] = mnew;
#pragma unroll
            for (int ni = 0; ni < 8; ni++) {
                oacc[ni][i * 2] *= corr;
                oacc[ni][i * 2 + 1] *= corr;
            }
        }

        // O += P V : C-fragment -> A-fragment via intra-quad shuffles
        const int src0 = (lane & ~3) | (tg >> 1);
        const bool odd = tg & 1;
#pragma unroll
        for (int ks = 0; ks < 8; ks++) {
            float p00 = __shfl_sync(0xffffffffu, sacc[ks][0], src0);
            float p01 = __shfl_sync(0xffffffffu, sacc[ks][1], src0);
            float p10 = __shfl_sync(0xffffffffu, sacc[ks][2], src0);
            float p11 = __shfl_sync(0xffffffffu, sacc[ks][3], src0);
            float q00 = __shfl_sync(0xffffffffu, sacc[ks][0], src0 + 2);
            float q01 = __shfl_sync(0xffffffffu, sacc[ks][1], src0 + 2);
            float q10 = __shfl_sync(0xffffffffu, sacc[ks][2], src0 + 2);
            float q11 = __shfl_sync(0xffffffffu, sacc[ks][3], src0 + 2);
            uint32_t a0 = __float_as_uint(f2tf32(odd ? p01 : p00));
            uint32_t a1 = __float_as_uint(f2tf32(odd ? p11 : p10));
            uint32_t a2 = __float_as_uint(f2tf32(odd ? q01 : q00));
            uint32_t a3 = __float_as_uint(f2tf32(odd ? q11 : q10));
            const int j0 = ks * 8;
#pragma unroll
            for (int ni = 0; ni < 8; ni++) {
                uint32_t b0 = __float_as_uint(Vb[(j0 + tg) * VSTR + ni * 8 + g]);
                uint32_t b1 = __float_as_uint(Vb[(j0 + tg + 4) * VSTR + ni * 8 + g]);
                mma_tf32(oacc[ni], a0, a1, a2, a3, b0, b1);
            }
        }
    }

    // Write UNNORMALIZED partials + (m, l)
    float* op = Op + (size_t)ch * 4096 * 512;
    const size_t rA = rowbase + qb * 128 + r0 + g;
#pragma unroll
    for (int ni = 0; ni < 8; ni++) {
        const int c = colh + ni * 8 + 2 * tg;
        *(float2*)(op + rA * D_MODEL + c) = make_float2(oacc[ni][0], oacc[ni][1]);
        *(float2*)(op + (rA + 8) * D_MODEL + c) = make_float2(oacc[ni][2], oacc[ni][3]);
    }
    if (tg == 0) {
        const size_t mlb = (size_t)(ch * 8 + h) * 4096;
        Mp[mlb + rA] = m[0];
        Lp[mlb + rA] = l[0];
        Mp[mlb + rA + 8] = m[1];
        Lp[mlb + rA + 8] = l[1];
    }
}

// ---------------------------------------------------------------------------
// Combine split-KV partials: exact softmax merge, then normalize.
// Thread handles one (row, head, col-pair). 256 thr/block.
// ---------------------------------------------------------------------------
__global__ void __launch_bounds__(256) combine_kernel(
    const float* __restrict__ Op, const float* __restrict__ Mp,
    const float* __restrict__ Lp, float* __restrict__ Og) {
    const int tid = threadIdx.x;
    const int u = blockIdx.x * 8 + (tid >> 5);  // (row, head) unit
    const int row = u >> 3, h = u & 7;
    const int j = (tid & 31) * 2;
    const int qb = (row >> 7) & 15;
    const int nch = (qb >> 2) + 1;

    float mv[4], lv[4];
    float mg = -1e30f;
#pragma unroll
    for (int c = 0; c < 4; c++)
        if (c < nch) {
            mv[c] = Mp[(size_t)(c * 8 + h) * 4096 + row];
            lv[c] = Lp[(size_t)(c * 8 + h) * 4096 + row];
            mg = fmaxf(mg, mv[c]);
        }
    float lg = 0.f;
    float2 o = make_float2(0.f, 0.f);
#pragma unroll
    for (int c = 0; c < 4; c++)
        if (c < nch) {
            const float sc = __expf(mv[c] - mg);
            lg += sc * lv[c];
            float2 p = *(const float2*)(Op + (size_t)c * 4096 * 512 +
                                        (size_t)row * 512 + h * 64 + j);
            o.x += sc * p.x;
            o.y += sc * p.y;
        }
    const float inv = 1.f / lg;
    *(float2*)(Og + (size_t)row * 512 + h * 64 + j) =
        make_float2(o.x * inv, o.y * inv);
}

// ---------------------------------------------------------------------------
extern "C" void kernel_launch(void* const* d_in, const int* in_sizes, int n_in,
                              void* d_out, int out_size) {
    const float* q  = (const float*)d_in[0];
    const float* k  = (const float*)d_in[1];
    const float* v  = (const float*)d_in[2];
    const float* wq = (const float*)d_in[3];
    const float* wk = (const float*)d_in[4];
    const float* wv = (const float*)d_in[5];
    const float* wo = (const float*)d_in[6];
    float* out = (float*)d_out;

    const int M = in_sizes[0] / D_MODEL;  // B*S = 4096
    const int B = 2;
    const int SEQ = M / B;                // 2048

    float *gq, *gk, *gv, *ga, *gop, *gm, *gl;
    cudaGetSymbolAddress((void**)&gq, g_q);
    cudaGetSymbolAddress((void**)&gk, g_k);
    cudaGetSymbolAddress((void**)&gv, g_v);
    cudaGetSymbolAddress((void**)&ga, g_att);
    cudaGetSymbolAddress((void**)&gop, g_op);
    cudaGetSymbolAddress((void**)&gm, g_m);
    cudaGetSymbolAddress((void**)&gl, g_l);

    cudaFuncSetAttribute(gemm_xwT<1>, cudaFuncAttributeMaxDynamicSharedMemorySize,
                         SMEM_GEMM);
    cudaFuncSetAttribute(gemm_xwT<0>, cudaFuncAttributeMaxDynamicSharedMemorySize,
                         SMEM_GEMM);
    cudaFuncSetAttribute(attn_kernel, cudaFuncAttributeMaxDynamicSharedMemorySize,
                         SMEM_ATTN);

    // Fused projection: q/k/v GEMMs in one launch (blockIdx.z selects).
    dim3 gg3(M / 128, D_MODEL / 128, 3);
    gemm_xwT<1><<<gg3, 256, SMEM_GEMM>>>(q, wq, gq, k, wk, gk, v, wv, gv);

    // Split-KV attention: 16 bh x 40 (qb, chunk) items.
    attn_kernel<<<16 * 40, 256, SMEM_ATTN>>>(gq, gk, gv, gop, gm, gl, SEQ);

    // Combine partials -> g_att
    combine_kernel<<<4096 * 8 / 8, 256>>>(gop, gm, gl, ga);

    // Output projection
    dim3 gg1(M / 128, D_MODEL / 128, 1);
    gemm_xwT<0><<<gg1, 256, SMEM_GEMM>>>(ga, wo, out, ga, wo, out, ga, wo, out);
}